// round 6
// baseline (speedup 1.0000x reference)
#include <cuda_runtime.h>

#define NN 100000
#define NE 1600000
#define NF 128
#define NC 64

// ---------------- device scratch (allocation-free) ----------------
__device__ float  g_deg[NN];
__device__ float  g_dinv[NN];
__device__ int    g_cnt[NN];          // edge counts, then scatter cursor
__device__ int    g_rowptr[NN + 1];   // CSR by target node
__device__ int    g_bsum[128];
__device__ int    g_boff[128];
__device__ int    g_src[NE];          // CSR source ids
__device__ float  g_wn[NE];           // normalized edge weights
__device__ float4 g_y0[NN * 16];      // x @ W^T   (100000 x 64)
__device__ float4 g_y1[NN * 16];      // after hop 1

// ---------------- init: deg = 1 (self loop), cnt = 0 ----------------
__global__ void k_init() {
    int i = blockIdx.x * blockDim.x + threadIdx.x;
    if (i < NN) { g_deg[i] = 1.0f; g_cnt[i] = 0; }
    if (i == 0) g_rowptr[NN] = NE;
}

// ---------------- edge pass 1: weighted in-degree + edge count ----------------
// edge_index is INT32 (JAX x64 disabled downcasts int64 -> int32).
__global__ void k_edge1(const int* __restrict__ ei, const float* __restrict__ ew) {
    int e = blockIdx.x * blockDim.x + threadIdx.x;
    if (e >= NE) return;
    int c = ei[NE + e];               // target node
    atomicAdd(&g_deg[c], ew[e]);
    atomicAdd(&g_cnt[c], 1);
}

__global__ void k_dinv() {
    int i = blockIdx.x * blockDim.x + threadIdx.x;
    if (i < NN) g_dinv[i] = rsqrtf(g_deg[i]);   // deg >= 1 always (self loop)
}

// ---------------- exclusive scan of g_cnt -> g_rowptr (3 kernels) ----------------
__global__ void k_scan1() {
    __shared__ int sh[256];
    int t = threadIdx.x;
    int base = blockIdx.x * 1024 + t * 4;
    int v0 = 0, v1 = 0, v2 = 0, v3 = 0;
    if (base + 0 < NN) v0 = g_cnt[base + 0];
    if (base + 1 < NN) v1 = g_cnt[base + 1];
    if (base + 2 < NN) v2 = g_cnt[base + 2];
    if (base + 3 < NN) v3 = g_cnt[base + 3];
    int s = v0 + v1 + v2 + v3;
    sh[t] = s;
    __syncthreads();
    for (int off = 1; off < 256; off <<= 1) {
        int add = (t >= off) ? sh[t - off] : 0;
        __syncthreads();
        sh[t] += add;
        __syncthreads();
    }
    int ex = sh[t] - s;
    if (base + 0 < NN) g_rowptr[base + 0] = ex;
    if (base + 1 < NN) g_rowptr[base + 1] = ex + v0;
    if (base + 2 < NN) g_rowptr[base + 2] = ex + v0 + v1;
    if (base + 3 < NN) g_rowptr[base + 3] = ex + v0 + v1 + v2;
    if (t == 255) g_bsum[blockIdx.x] = sh[255];
}

__global__ void k_scan2(int nb) {
    __shared__ int sh[128];
    int t = threadIdx.x;
    int v = (t < nb) ? g_bsum[t] : 0;
    sh[t] = v;
    __syncthreads();
    for (int off = 1; off < 128; off <<= 1) {
        int add = (t >= off) ? sh[t - off] : 0;
        __syncthreads();
        sh[t] += add;
        __syncthreads();
    }
    if (t < nb) g_boff[t] = sh[t] - v;
}

__global__ void k_scan3() {
    int off = g_boff[blockIdx.x];
    int base = blockIdx.x * 1024 + threadIdx.x * 4;
#pragma unroll
    for (int i = 0; i < 4; i++) {
        int idx = base + i;
        if (idx < NN) {
            int v = g_rowptr[idx] + off;
            g_rowptr[idx] = v;
            g_cnt[idx] = v;   // cursor for scatter
        }
    }
}

// ---------------- scatter edges into CSR with normalized weights ----------------
__global__ void k_scatter(const int* __restrict__ ei, const float* __restrict__ ew) {
    int e = blockIdx.x * blockDim.x + threadIdx.x;
    if (e >= NE) return;
    int r = ei[e];
    int c = ei[NE + e];
    int pos = atomicAdd(&g_cnt[c], 1);
    g_src[pos] = r;
    g_wn[pos]  = g_dinv[r] * ew[e] * g_dinv[c];
}

// ---------------- GEMM: y0 = x @ W^T  (100000x128 @ 128x64) ----------------
// 64 nodes x 64 classes per block, 256 threads, 4x4 register tile.
__global__ void k_gemm(const float* __restrict__ x, const float* __restrict__ W) {
    __shared__ float xs[64 * 33];   // [node][k], padded stride 33
    __shared__ float ws[64 * 33];   // [class][k], padded stride 33
    float* y = (float*)g_y0;
    int tid = threadIdx.x;
    int tx = tid & 15;              // class lane: classes tx, tx+16, tx+32, tx+48
    int ty = tid >> 4;              // node lane:  nodes  ty, ty+16, ty+32, ty+48
    int n0 = blockIdx.x * 64;

    float acc[4][4];
#pragma unroll
    for (int i = 0; i < 4; i++)
#pragma unroll
        for (int j = 0; j < 4; j++) acc[i][j] = 0.0f;

    for (int kt = 0; kt < NF; kt += 32) {
        for (int i = tid; i < 64 * 32; i += 256) {
            int r = i >> 5, k = i & 31;
            int xr = n0 + r; if (xr >= NN) xr = NN - 1;
            xs[r * 33 + k] = x[(size_t)xr * NF + kt + k];
        }
        for (int i = tid; i < 64 * 32; i += 256) {
            int c = i >> 5, k = i & 31;
            ws[c * 33 + k] = W[c * NF + kt + k];
        }
        __syncthreads();
#pragma unroll
        for (int k = 0; k < 32; k++) {
            float xv[4], wv[4];
#pragma unroll
            for (int i = 0; i < 4; i++) xv[i] = xs[(ty + 16 * i) * 33 + k];
#pragma unroll
            for (int j = 0; j < 4; j++) wv[j] = ws[(tx + 16 * j) * 33 + k];
#pragma unroll
            for (int i = 0; i < 4; i++)
#pragma unroll
                for (int j = 0; j < 4; j++)
                    acc[i][j] = fmaf(xv[i], wv[j], acc[i][j]);
        }
        __syncthreads();
    }
#pragma unroll
    for (int i = 0; i < 4; i++) {
        int node = n0 + ty + 16 * i;
        if (node < NN) {
#pragma unroll
            for (int j = 0; j < 4; j++)
                y[(size_t)node * NC + tx + 16 * j] = acc[i][j];
        }
    }
}

// ---------------- SpMM hops: out = A_norm @ in (64-wide features) ----------------
// 16 threads per node; each thread owns one float4 feature chunk.
__global__ void k_hop1() {
    int gid = blockIdx.x * blockDim.x + threadIdx.x;
    int node = gid >> 4;
    if (node >= NN) return;
    int lane = gid & 15;

    int s = g_rowptr[node];
    int e = g_rowptr[node + 1];
    float dv = g_dinv[node];
    float sw = dv * dv;                      // self-loop normalized weight
    float4 xv = g_y0[node * 16 + lane];
    float4 acc;
    acc.x = sw * xv.x; acc.y = sw * xv.y; acc.z = sw * xv.z; acc.w = sw * xv.w;

    for (int i = s; i < e; i++) {
        int u = g_src[i];
        float wv = g_wn[i];
        float4 v = g_y0[u * 16 + lane];
        acc.x = fmaf(wv, v.x, acc.x);
        acc.y = fmaf(wv, v.y, acc.y);
        acc.z = fmaf(wv, v.z, acc.z);
        acc.w = fmaf(wv, v.w, acc.w);
    }
    g_y1[node * 16 + lane] = acc;
}

__global__ void k_hop2(float4* __restrict__ out, const float* __restrict__ bias) {
    int gid = blockIdx.x * blockDim.x + threadIdx.x;
    int node = gid >> 4;
    if (node >= NN) return;
    int lane = gid & 15;

    int s = g_rowptr[node];
    int e = g_rowptr[node + 1];
    float dv = g_dinv[node];
    float sw = dv * dv;
    float4 xv = g_y1[node * 16 + lane];
    float4 acc;
    acc.x = sw * xv.x; acc.y = sw * xv.y; acc.z = sw * xv.z; acc.w = sw * xv.w;

    for (int i = s; i < e; i++) {
        int u = g_src[i];
        float wv = g_wn[i];
        float4 v = g_y1[u * 16 + lane];
        acc.x = fmaf(wv, v.x, acc.x);
        acc.y = fmaf(wv, v.y, acc.y);
        acc.z = fmaf(wv, v.z, acc.z);
        acc.w = fmaf(wv, v.w, acc.w);
    }
    acc.x += bias[lane * 4 + 0];
    acc.y += bias[lane * 4 + 1];
    acc.z += bias[lane * 4 + 2];
    acc.w += bias[lane * 4 + 3];
    out[node * 16 + lane] = acc;
}

// ---------------- launch ----------------
extern "C" void kernel_launch(void* const* d_in, const int* in_sizes, int n_in,
                              void* d_out, int out_size) {
    const float* x    = (const float*)d_in[0];
    const int*   ei   = (const int*)d_in[1];     // int32 edge_index [2, NE]
    const float* ew   = (const float*)d_in[2];
    const float* Wl   = (const float*)d_in[3];
    const float* bias = (const float*)d_in[4];
    float4* out = (float4*)d_out;

    const int NB_N  = (NN + 255) / 256;        // 391
    const int NB_E  = (NE + 255) / 256;        // 6250
    const int NB_SC = (NN + 1023) / 1024;      // 98
    const int NB_H  = (NN * 16 + 255) / 256;   // 6250
    const int NB_G  = (NN + 63) / 64;          // 1563

    k_init<<<NB_N, 256>>>();
    k_edge1<<<NB_E, 256>>>(ei, ew);
    k_dinv<<<NB_N, 256>>>();
    k_scan1<<<NB_SC, 256>>>();
    k_scan2<<<1, 128>>>(NB_SC);
    k_scan3<<<NB_SC, 256>>>();
    k_scatter<<<NB_E, 256>>>(ei, ew);
    k_gemm<<<NB_G, 256>>>(x, Wl);
    k_hop1<<<NB_H, 256>>>();
    k_hop2<<<NB_H, 256>>>(out, bias);
}

// round 7
// speedup vs baseline: 1.2284x; 1.2284x over previous
#include <cuda_runtime.h>

#define NN 100000
#define NE 1600000
#define NF 128
#define NC 64

// ---------------- device scratch (allocation-free) ----------------
__device__ float  g_deg[NN];
__device__ float  g_dinv[NN];
__device__ int    g_cnt[NN];          // edge counts, then scatter cursor
__device__ int    g_rowptr[NN + 1];   // CSR by target node
__device__ int    g_bsum[128];
__device__ int    g_boff[128];
__device__ int2   g_edge[NE];         // packed (src, weight-as-int)
__device__ float4 g_y0[NN * 16];      // x @ W^T   (100000 x 64)
__device__ float4 g_y1[NN * 16];      // after hop 1

// ---------------- init: deg = 1 (self loop), cnt = 0 ----------------
__global__ void k_init() {
    int i = blockIdx.x * blockDim.x + threadIdx.x;
    if (i < NN) { g_deg[i] = 1.0f; g_cnt[i] = 0; }
    if (i == 0) g_rowptr[NN] = NE;
}

// ---------------- edge pass 1: weighted in-degree + edge count ----------------
__global__ void k_edge1(const int* __restrict__ ei, const float* __restrict__ ew) {
    int e = blockIdx.x * blockDim.x + threadIdx.x;
    if (e >= NE) return;
    int c = ei[NE + e];               // target node
    atomicAdd(&g_deg[c], ew[e]);
    atomicAdd(&g_cnt[c], 1);
}

// ---------------- exclusive scan of g_cnt -> g_rowptr (3 kernels) ----------------
__global__ void k_scan1() {
    __shared__ int sh[256];
    int t = threadIdx.x;
    int base = blockIdx.x * 1024 + t * 4;
    int v0 = 0, v1 = 0, v2 = 0, v3 = 0;
    if (base + 0 < NN) v0 = g_cnt[base + 0];
    if (base + 1 < NN) v1 = g_cnt[base + 1];
    if (base + 2 < NN) v2 = g_cnt[base + 2];
    if (base + 3 < NN) v3 = g_cnt[base + 3];
    int s = v0 + v1 + v2 + v3;
    sh[t] = s;
    __syncthreads();
    for (int off = 1; off < 256; off <<= 1) {
        int add = (t >= off) ? sh[t - off] : 0;
        __syncthreads();
        sh[t] += add;
        __syncthreads();
    }
    int ex = sh[t] - s;
    if (base + 0 < NN) g_rowptr[base + 0] = ex;
    if (base + 1 < NN) g_rowptr[base + 1] = ex + v0;
    if (base + 2 < NN) g_rowptr[base + 2] = ex + v0 + v1;
    if (base + 3 < NN) g_rowptr[base + 3] = ex + v0 + v1 + v2;
    if (t == 255) g_bsum[blockIdx.x] = sh[255];
}

__global__ void k_scan2(int nb) {
    __shared__ int sh[128];
    int t = threadIdx.x;
    int v = (t < nb) ? g_bsum[t] : 0;
    sh[t] = v;
    __syncthreads();
    for (int off = 1; off < 128; off <<= 1) {
        int add = (t >= off) ? sh[t - off] : 0;
        __syncthreads();
        sh[t] += add;
        __syncthreads();
    }
    if (t < nb) g_boff[t] = sh[t] - v;
}

// scan3 also computes dinv (fused elementwise pass)
__global__ void k_scan3() {
    int off = g_boff[blockIdx.x];
    int base = blockIdx.x * 1024 + threadIdx.x * 4;
#pragma unroll
    for (int i = 0; i < 4; i++) {
        int idx = base + i;
        if (idx < NN) {
            int v = g_rowptr[idx] + off;
            g_rowptr[idx] = v;
            g_cnt[idx] = v;                      // cursor for scatter
            g_dinv[idx] = rsqrtf(g_deg[idx]);    // deg >= 1 always
        }
    }
}

// ---------------- scatter edges into CSR with normalized weights (packed) -------
__global__ void k_scatter(const int* __restrict__ ei, const float* __restrict__ ew) {
    int e = blockIdx.x * blockDim.x + threadIdx.x;
    if (e >= NE) return;
    int r = ei[e];
    int c = ei[NE + e];
    int pos = atomicAdd(&g_cnt[c], 1);
    float wn = g_dinv[r] * ew[e] * g_dinv[c];
    g_edge[pos] = make_int2(r, __float_as_int(wn));
}

// ---------------- GEMM: y0 = x @ W^T  (100000x128 @ 128x64) ----------------
// 128 nodes x 64 classes per block, 256 threads (16x16), 8x4 register tile.
// Shared tiles stored k-major so inner loop is 3x LDS.128 + 32 FFMA.
#define XS_STRIDE 132   // floats per k-row (128 + 4 pad), 16B-aligned
#define WS_STRIDE 68    // floats per k-row (64 + 4 pad), 16B-aligned
__global__ void k_gemm(const float* __restrict__ x, const float* __restrict__ W) {
    __shared__ float4 xs4[(32 * XS_STRIDE) / 4];
    __shared__ float4 ws4[(32 * WS_STRIDE) / 4];
    float* xs = (float*)xs4;
    float* ws = (float*)ws4;
    int tid = threadIdx.x;
    int tx = tid & 15;              // class group: classes tx*4 .. tx*4+3
    int ty = tid >> 4;              // node group:  nodes  ty*8 .. ty*8+7
    int n0 = blockIdx.x * 128;

    float acc[8][4];
#pragma unroll
    for (int i = 0; i < 8; i++)
#pragma unroll
        for (int j = 0; j < 4; j++) acc[i][j] = 0.0f;

    for (int kt = 0; kt < NF; kt += 32) {
        // stage x tile transposed: xs[k][node], coalesced reads along k
        for (int i = tid; i < 128 * 32; i += 256) {
            int node = i >> 5, k = i & 31;
            int xr = n0 + node; if (xr >= NN) xr = NN - 1;
            xs[k * XS_STRIDE + node] = x[(size_t)xr * NF + kt + k];
        }
        // stage W tile transposed: ws[k][class]
        for (int i = tid; i < 64 * 32; i += 256) {
            int c = i >> 5, k = i & 31;
            ws[k * WS_STRIDE + c] = W[c * NF + kt + k];
        }
        __syncthreads();
#pragma unroll
        for (int k = 0; k < 32; k++) {
            const float4* xr4 = (const float4*)(xs + k * XS_STRIDE + ty * 8);
            float4 xa = xr4[0];
            float4 xb = xr4[1];
            float4 wv = *(const float4*)(ws + k * WS_STRIDE + tx * 4);
            float xv[8] = {xa.x, xa.y, xa.z, xa.w, xb.x, xb.y, xb.z, xb.w};
#pragma unroll
            for (int i = 0; i < 8; i++) {
                acc[i][0] = fmaf(xv[i], wv.x, acc[i][0]);
                acc[i][1] = fmaf(xv[i], wv.y, acc[i][1]);
                acc[i][2] = fmaf(xv[i], wv.z, acc[i][2]);
                acc[i][3] = fmaf(xv[i], wv.w, acc[i][3]);
            }
        }
        __syncthreads();
    }
#pragma unroll
    for (int i = 0; i < 8; i++) {
        int node = n0 + ty * 8 + i;
        if (node < NN) {
            float4 v = make_float4(acc[i][0], acc[i][1], acc[i][2], acc[i][3]);
            g_y0[node * 16 + tx] = v;
        }
    }
}

// ---------------- SpMM hops: out = A_norm @ in (64-wide features) ----------------
// 16 threads per node; each thread owns one float4 feature chunk.
__global__ void k_hop1() {
    int gid = blockIdx.x * blockDim.x + threadIdx.x;
    int node = gid >> 4;
    if (node >= NN) return;
    int lane = gid & 15;

    int s = g_rowptr[node];
    int e = g_rowptr[node + 1];
    float dv = g_dinv[node];
    float sw = dv * dv;                      // self-loop normalized weight
    float4 xv = g_y0[node * 16 + lane];
    float4 acc;
    acc.x = sw * xv.x; acc.y = sw * xv.y; acc.z = sw * xv.z; acc.w = sw * xv.w;

#pragma unroll 2
    for (int i = s; i < e; i++) {
        int2 m = g_edge[i];
        float wv = __int_as_float(m.y);
        float4 v = g_y0[m.x * 16 + lane];
        acc.x = fmaf(wv, v.x, acc.x);
        acc.y = fmaf(wv, v.y, acc.y);
        acc.z = fmaf(wv, v.z, acc.z);
        acc.w = fmaf(wv, v.w, acc.w);
    }
    g_y1[node * 16 + lane] = acc;
}

__global__ void k_hop2(float4* __restrict__ out, const float4* __restrict__ bias) {
    int gid = blockIdx.x * blockDim.x + threadIdx.x;
    int node = gid >> 4;
    if (node >= NN) return;
    int lane = gid & 15;

    int s = g_rowptr[node];
    int e = g_rowptr[node + 1];
    float dv = g_dinv[node];
    float sw = dv * dv;
    float4 xv = g_y1[node * 16 + lane];
    float4 acc;
    acc.x = sw * xv.x; acc.y = sw * xv.y; acc.z = sw * xv.z; acc.w = sw * xv.w;

#pragma unroll 2
    for (int i = s; i < e; i++) {
        int2 m = g_edge[i];
        float wv = __int_as_float(m.y);
        float4 v = g_y1[m.x * 16 + lane];
        acc.x = fmaf(wv, v.x, acc.x);
        acc.y = fmaf(wv, v.y, acc.y);
        acc.z = fmaf(wv, v.z, acc.z);
        acc.w = fmaf(wv, v.w, acc.w);
    }
    float4 b = bias[lane];
    acc.x += b.x; acc.y += b.y; acc.z += b.z; acc.w += b.w;
    out[node * 16 + lane] = acc;
}

// ---------------- launch: CSR build (default stream) || GEMM (side stream) ------
extern "C" void kernel_launch(void* const* d_in, const int* in_sizes, int n_in,
                              void* d_out, int out_size) {
    const float* x    = (const float*)d_in[0];
    const int*   ei   = (const int*)d_in[1];     // int32 edge_index [2, NE]
    const float* ew   = (const float*)d_in[2];
    const float* Wl   = (const float*)d_in[3];
    const float* bias = (const float*)d_in[4];
    float4* out = (float4*)d_out;

    const int NB_N  = (NN + 255) / 256;        // 391
    const int NB_E  = (NE + 255) / 256;        // 6250
    const int NB_SC = (NN + 1023) / 1024;      // 98
    const int NB_H  = (NN * 16 + 255) / 256;   // 6250
    const int NB_G  = (NN + 127) / 128;        // 782

    cudaStream_t s2;
    cudaEvent_t evFork, evJoin;
    cudaStreamCreateWithFlags(&s2, cudaStreamNonBlocking);
    cudaEventCreateWithFlags(&evFork, cudaEventDisableTiming);
    cudaEventCreateWithFlags(&evJoin, cudaEventDisableTiming);

    // fork: GEMM is independent of the CSR-build chain
    cudaEventRecord(evFork, 0);
    cudaStreamWaitEvent(s2, evFork, 0);
    k_gemm<<<NB_G, 256, 0, s2>>>(x, Wl);
    cudaEventRecord(evJoin, s2);

    // CSR build on default stream
    k_init<<<NB_N, 256>>>();
    k_edge1<<<NB_E, 256>>>(ei, ew);
    k_scan1<<<NB_SC, 256>>>();
    k_scan2<<<1, 128>>>(NB_SC);
    k_scan3<<<NB_SC, 256>>>();
    k_scatter<<<NB_E, 256>>>(ei, ew);

    // join, then hops
    cudaStreamWaitEvent(0, evJoin, 0);
    k_hop1<<<NB_H, 256>>>();
    k_hop2<<<NB_H, 256>>>(out, (const float4*)bias);

    // clean up only when not inside graph capture
    cudaStreamCaptureStatus st = cudaStreamCaptureStatusNone;
    cudaStreamIsCapturing(0, &st);
    if (st == cudaStreamCaptureStatusNone) {
        cudaEventDestroy(evFork);
        cudaEventDestroy(evJoin);
        cudaStreamDestroy(s2);
    }
}

// round 8
// speedup vs baseline: 1.3439x; 1.0940x over previous
#include <cuda_runtime.h>
#include <cuda_fp16.h>

#define NN 100000
#define NE 1600000
#define NF 128
#define NC 64

// ---------------- device scratch (allocation-free) ----------------
__device__ unsigned long long g_pk[NN];   // bits[44+): edge count, bits[0:44): sum(w)*2^32
__device__ float  g_dinv[NN];
__device__ int    g_cnt[NN];              // scatter cursor
__device__ int    g_rowptr[NN + 1];       // CSR by target node
__device__ int    g_bsum[128];
__device__ int    g_boff[128];
__device__ int2   g_edge[NE];             // packed (src, weight-as-int)
__device__ uint2  g_h0[NN * 16];          // x @ W^T as half2 pairs (64 feats = 128B/row)
__device__ uint2  g_h1[NN * 16];          // after hop 1 (half)

// half<->float helpers (register-level reinterpret)
static __device__ __forceinline__ float2 u2f(unsigned v) {
    __half2 h = *reinterpret_cast<__half2*>(&v);
    return __half22float2(h);
}
static __device__ __forceinline__ unsigned f2u(float a, float b) {
    __half2 h = __floats2half2_rn(a, b);
    return *reinterpret_cast<unsigned*>(&h);
}

// ---------------- init: pk = self-loop weight 1.0 (count 0) ----------------
__global__ void k_init() {
    int i = blockIdx.x * blockDim.x + threadIdx.x;
    if (i < NN) g_pk[i] = (1ULL << 32);       // w=1.0 in 32.32 fixed point
    if (i == 0) g_rowptr[NN] = NE;
}

// ---------------- edge pass: ONE u64 atomic = count + weighted degree ----------
__global__ void k_edge1(const int* __restrict__ ei, const float* __restrict__ ew) {
    int e = blockIdx.x * blockDim.x + threadIdx.x;
    if (e >= NE) return;
    int c = ei[NE + e];                       // target node
    unsigned long long v = (1ULL << 44)
        + (unsigned long long)(ew[e] * 4294967296.0f);
    atomicAdd(&g_pk[c], v);
}

// ---------------- exclusive scan of counts -> g_rowptr (3 kernels) -------------
__global__ void k_scan1() {
    __shared__ int sh[256];
    int t = threadIdx.x;
    int base = blockIdx.x * 1024 + t * 4;
    int v0 = 0, v1 = 0, v2 = 0, v3 = 0;
    if (base + 0 < NN) v0 = (int)(g_pk[base + 0] >> 44);
    if (base + 1 < NN) v1 = (int)(g_pk[base + 1] >> 44);
    if (base + 2 < NN) v2 = (int)(g_pk[base + 2] >> 44);
    if (base + 3 < NN) v3 = (int)(g_pk[base + 3] >> 44);
    int s = v0 + v1 + v2 + v3;
    sh[t] = s;
    __syncthreads();
    for (int off = 1; off < 256; off <<= 1) {
        int add = (t >= off) ? sh[t - off] : 0;
        __syncthreads();
        sh[t] += add;
        __syncthreads();
    }
    int ex = sh[t] - s;
    if (base + 0 < NN) g_rowptr[base + 0] = ex;
    if (base + 1 < NN) g_rowptr[base + 1] = ex + v0;
    if (base + 2 < NN) g_rowptr[base + 2] = ex + v0 + v1;
    if (base + 3 < NN) g_rowptr[base + 3] = ex + v0 + v1 + v2;
    if (t == 255) g_bsum[blockIdx.x] = sh[255];
}

__global__ void k_scan2(int nb) {
    __shared__ int sh[128];
    int t = threadIdx.x;
    int v = (t < nb) ? g_bsum[t] : 0;
    sh[t] = v;
    __syncthreads();
    for (int off = 1; off < 128; off <<= 1) {
        int add = (t >= off) ? sh[t - off] : 0;
        __syncthreads();
        sh[t] += add;
        __syncthreads();
    }
    if (t < nb) g_boff[t] = sh[t] - v;
}

// scan3: finalize rowptr, init cursor, decode dinv from packed degree
__global__ void k_scan3() {
    int off = g_boff[blockIdx.x];
    int base = blockIdx.x * 1024 + threadIdx.x * 4;
#pragma unroll
    for (int i = 0; i < 4; i++) {
        int idx = base + i;
        if (idx < NN) {
            int v = g_rowptr[idx] + off;
            g_rowptr[idx] = v;
            g_cnt[idx] = v;
            unsigned long long low = g_pk[idx] & ((1ULL << 44) - 1);
            float deg = (float)low * 2.3283064365386963e-10f;  // * 2^-32, >= 1.0
            g_dinv[idx] = rsqrtf(deg);
        }
    }
}

// ---------------- scatter edges into CSR with normalized weights (packed) -------
__global__ void k_scatter(const int* __restrict__ ei, const float* __restrict__ ew) {
    int e = blockIdx.x * blockDim.x + threadIdx.x;
    if (e >= NE) return;
    int r = ei[e];
    int c = ei[NE + e];
    int pos = atomicAdd(&g_cnt[c], 1);
    float wn = g_dinv[r] * ew[e] * g_dinv[c];
    g_edge[pos] = make_int2(r, __float_as_int(wn));
}

// ---------------- GEMM: y0 = x @ W^T -> half2  (100000x128 @ 128x64) ------------
#define XS_STRIDE 132
#define WS_STRIDE 68
__global__ void k_gemm(const float* __restrict__ x, const float* __restrict__ W) {
    __shared__ float4 xs4[(32 * XS_STRIDE) / 4];
    __shared__ float4 ws4[(32 * WS_STRIDE) / 4];
    float* xs = (float*)xs4;
    float* ws = (float*)ws4;
    int tid = threadIdx.x;
    int tx = tid & 15;              // class group: classes tx*4 .. tx*4+3
    int ty = tid >> 4;              // node group:  nodes  ty*8 .. ty*8+7
    int n0 = blockIdx.x * 128;

    float acc[8][4];
#pragma unroll
    for (int i = 0; i < 8; i++)
#pragma unroll
        for (int j = 0; j < 4; j++) acc[i][j] = 0.0f;

    for (int kt = 0; kt < NF; kt += 32) {
        for (int i = tid; i < 128 * 32; i += 256) {
            int node = i >> 5, k = i & 31;
            int xr = n0 + node; if (xr >= NN) xr = NN - 1;
            xs[k * XS_STRIDE + node] = x[(size_t)xr * NF + kt + k];
        }
        for (int i = tid; i < 64 * 32; i += 256) {
            int c = i >> 5, k = i & 31;
            ws[k * WS_STRIDE + c] = W[c * NF + kt + k];
        }
        __syncthreads();
#pragma unroll
        for (int k = 0; k < 32; k++) {
            const float4* xr4 = (const float4*)(xs + k * XS_STRIDE + ty * 8);
            float4 xa = xr4[0];
            float4 xb = xr4[1];
            float4 wv = *(const float4*)(ws + k * WS_STRIDE + tx * 4);
            float xv[8] = {xa.x, xa.y, xa.z, xa.w, xb.x, xb.y, xb.z, xb.w};
#pragma unroll
            for (int i = 0; i < 8; i++) {
                acc[i][0] = fmaf(xv[i], wv.x, acc[i][0]);
                acc[i][1] = fmaf(xv[i], wv.y, acc[i][1]);
                acc[i][2] = fmaf(xv[i], wv.z, acc[i][2]);
                acc[i][3] = fmaf(xv[i], wv.w, acc[i][3]);
            }
        }
        __syncthreads();
    }
#pragma unroll
    for (int i = 0; i < 8; i++) {
        int node = n0 + ty * 8 + i;
        if (node < NN)
            g_h0[node * 16 + tx] = make_uint2(f2u(acc[i][0], acc[i][1]),
                                              f2u(acc[i][2], acc[i][3]));
    }
}

// ---------------- SpMM hops (half rows, fp32 accumulate) ------------------------
// 16 threads/node; lane owns feats {4*lane .. 4*lane+3} = one uint2 (8B).
__global__ void k_hop1() {
    int gid = blockIdx.x * blockDim.x + threadIdx.x;
    int node = gid >> 4;
    if (node >= NN) return;
    int lane = gid & 15;

    int s = g_rowptr[node];
    int e = g_rowptr[node + 1];
    float dv = g_dinv[node];
    float sw = dv * dv;
    uint2 p = g_h0[node * 16 + lane];
    float2 f0 = u2f(p.x), f1 = u2f(p.y);
    float a0 = sw * f0.x, a1 = sw * f0.y, a2 = sw * f1.x, a3 = sw * f1.y;

#pragma unroll 2
    for (int i = s; i < e; i++) {
        int2 m = g_edge[i];
        float w = __int_as_float(m.y);
        uint2 q = g_h0[m.x * 16 + lane];
        float2 g0 = u2f(q.x), g1 = u2f(q.y);
        a0 = fmaf(w, g0.x, a0);
        a1 = fmaf(w, g0.y, a1);
        a2 = fmaf(w, g1.x, a2);
        a3 = fmaf(w, g1.y, a3);
    }
    g_h1[node * 16 + lane] = make_uint2(f2u(a0, a1), f2u(a2, a3));
}

__global__ void k_hop2(float4* __restrict__ out, const float4* __restrict__ bias) {
    int gid = blockIdx.x * blockDim.x + threadIdx.x;
    int node = gid >> 4;
    if (node >= NN) return;
    int lane = gid & 15;

    int s = g_rowptr[node];
    int e = g_rowptr[node + 1];
    float dv = g_dinv[node];
    float sw = dv * dv;
    uint2 p = g_h1[node * 16 + lane];
    float2 f0 = u2f(p.x), f1 = u2f(p.y);
    float a0 = sw * f0.x, a1 = sw * f0.y, a2 = sw * f1.x, a3 = sw * f1.y;

#pragma unroll 2
    for (int i = s; i < e; i++) {
        int2 m = g_edge[i];
        float w = __int_as_float(m.y);
        uint2 q = g_h1[m.x * 16 + lane];
        float2 g0 = u2f(q.x), g1 = u2f(q.y);
        a0 = fmaf(w, g0.x, a0);
        a1 = fmaf(w, g0.y, a1);
        a2 = fmaf(w, g1.x, a2);
        a3 = fmaf(w, g1.y, a3);
    }
    float4 b = bias[lane];
    out[node * 16 + lane] = make_float4(a0 + b.x, a1 + b.y, a2 + b.z, a3 + b.w);
}

// ---------------- launch: CSR build (default stream) || GEMM (side stream) ------
extern "C" void kernel_launch(void* const* d_in, const int* in_sizes, int n_in,
                              void* d_out, int out_size) {
    const float* x    = (const float*)d_in[0];
    const int*   ei   = (const int*)d_in[1];     // int32 edge_index [2, NE]
    const float* ew   = (const float*)d_in[2];
    const float* Wl   = (const float*)d_in[3];
    const float* bias = (const float*)d_in[4];
    float4* out = (float4*)d_out;

    const int NB_N  = (NN + 255) / 256;        // 391
    const int NB_E  = (NE + 255) / 256;        // 6250
    const int NB_SC = (NN + 1023) / 1024;      // 98
    const int NB_H  = (NN * 16 + 255) / 256;   // 6250
    const int NB_G  = (NN + 127) / 128;        // 782

    cudaStream_t s2;
    cudaEvent_t evFork, evJoin;
    cudaStreamCreateWithFlags(&s2, cudaStreamNonBlocking);
    cudaEventCreateWithFlags(&evFork, cudaEventDisableTiming);
    cudaEventCreateWithFlags(&evJoin, cudaEventDisableTiming);

    // fork: GEMM independent of CSR build
    cudaEventRecord(evFork, 0);
    cudaStreamWaitEvent(s2, evFork, 0);
    k_gemm<<<NB_G, 256, 0, s2>>>(x, Wl);
    cudaEventRecord(evJoin, s2);

    // CSR build on default stream
    k_init<<<NB_N, 256>>>();
    k_edge1<<<NB_E, 256>>>(ei, ew);
    k_scan1<<<NB_SC, 256>>>();
    k_scan2<<<1, 128>>>(NB_SC);
    k_scan3<<<NB_SC, 256>>>();
    k_scatter<<<NB_E, 256>>>(ei, ew);

    // join, then hops
    cudaStreamWaitEvent(0, evJoin, 0);
    k_hop1<<<NB_H, 256>>>();
    k_hop2<<<NB_H, 256>>>(out, (const float4*)bias);

    cudaStreamCaptureStatus st = cudaStreamCaptureStatusNone;
    cudaStreamIsCapturing(0, &st);
    if (st == cudaStreamCaptureStatusNone) {
        cudaEventDestroy(evFork);
        cudaEventDestroy(evJoin);
        cudaStreamDestroy(s2);
    }
}